// round 2
// baseline (speedup 1.0000x reference)
#include <cuda_runtime.h>
#include <math.h>

#define NC 19
#define ND 256
#define NB 8
#define HW 16384              // 128*128
#define NPIX (NB*HW)          // 131072
#define NCHUNK 4
#define DCH (ND/NCHUNK)       // 64
#define EPS 1e-8f

// ---------------- static scratch (no runtime allocation) ----------------
__device__ float g_S[NC*ND];          // class sums
__device__ float g_counts[NC];
__device__ float g_centers[NC*ND];
__device__ float g_ncen[NC];
__device__ float g_dotp[NCHUNK*NPIX]; // per-pixel partial dot(feat, center)
__device__ float g_nsqp[NCHUNK*NPIX]; // per-pixel partial ||feat||^2
__device__ float g_percls[NC];
__device__ float g_diff;

// ---------------- kernel 0: zero accumulators ----------------
__global__ void k_zero() {
    int i = blockIdx.x * blockDim.x + threadIdx.x;
    if (i < NC*ND) g_S[i] = 0.f;
    if (i < NC) { g_counts[i] = 0.f; g_percls[i] = 0.f; }
}

// ---------------- kernel 1: class sums (+counts on d==0 planes) ----------------
// one block per (b,d) plane; 256 threads; float4 loads; privatized smem bins
__global__ __launch_bounds__(256) void k_pass1(const float4* __restrict__ X,
                                               const int4* __restrict__ T) {
    __shared__ float sbin[16][20];
    __shared__ int   scnt[20];
    const int tid = threadIdx.x;
    const int b = blockIdx.x >> 8;
    const int d = blockIdx.x & 255;
    const int w2 = ((tid >> 5) << 1) | (tid & 1);   // warp*2 + lane parity

    for (int i = tid; i < 16*20; i += 256) ((float*)sbin)[i] = 0.f;
    if (tid < 20) scnt[tid] = 0;
    __syncthreads();

    const float4* plane = X + (size_t)(b*ND + d) * (HW/4);
    const int4*   labs  = T + (size_t)b * (HW/4);
    const bool do_cnt = (d == 0);

    #pragma unroll 1
    for (int k = 0; k < 16; k += 4) {
        float4 v0 = plane[tid + (k+0)*256];
        float4 v1 = plane[tid + (k+1)*256];
        float4 v2 = plane[tid + (k+2)*256];
        float4 v3 = plane[tid + (k+3)*256];
        int4 l0 = labs[tid + (k+0)*256];
        int4 l1 = labs[tid + (k+1)*256];
        int4 l2 = labs[tid + (k+2)*256];
        int4 l3 = labs[tid + (k+3)*256];
        atomicAdd(&sbin[w2][l0.x], v0.x); atomicAdd(&sbin[w2][l0.y], v0.y);
        atomicAdd(&sbin[w2][l0.z], v0.z); atomicAdd(&sbin[w2][l0.w], v0.w);
        atomicAdd(&sbin[w2][l1.x], v1.x); atomicAdd(&sbin[w2][l1.y], v1.y);
        atomicAdd(&sbin[w2][l1.z], v1.z); atomicAdd(&sbin[w2][l1.w], v1.w);
        atomicAdd(&sbin[w2][l2.x], v2.x); atomicAdd(&sbin[w2][l2.y], v2.y);
        atomicAdd(&sbin[w2][l2.z], v2.z); atomicAdd(&sbin[w2][l2.w], v2.w);
        atomicAdd(&sbin[w2][l3.x], v3.x); atomicAdd(&sbin[w2][l3.y], v3.y);
        atomicAdd(&sbin[w2][l3.z], v3.z); atomicAdd(&sbin[w2][l3.w], v3.w);
        if (do_cnt) {
            atomicAdd(&scnt[l0.x],1); atomicAdd(&scnt[l0.y],1);
            atomicAdd(&scnt[l0.z],1); atomicAdd(&scnt[l0.w],1);
            atomicAdd(&scnt[l1.x],1); atomicAdd(&scnt[l1.y],1);
            atomicAdd(&scnt[l1.z],1); atomicAdd(&scnt[l1.w],1);
            atomicAdd(&scnt[l2.x],1); atomicAdd(&scnt[l2.y],1);
            atomicAdd(&scnt[l2.z],1); atomicAdd(&scnt[l2.w],1);
            atomicAdd(&scnt[l3.x],1); atomicAdd(&scnt[l3.y],1);
            atomicAdd(&scnt[l3.z],1); atomicAdd(&scnt[l3.w],1);
        }
    }
    __syncthreads();
    if (tid < NC) {
        float s = 0.f;
        #pragma unroll
        for (int w = 0; w < 16; w++) s += sbin[w][tid];
        atomicAdd(&g_S[tid*ND + d], s);
        if (do_cnt) atomicAdd(&g_counts[tid], (float)scnt[tid]);
    }
}

// ---------------- kernel 2: centers, norms, diff_loss ----------------
__global__ __launch_bounds__(256) void k_centers() {
    __shared__ float cen[NC][ND+1];
    __shared__ float cnt_s[NC];
    __shared__ float ncen_s[NC];
    __shared__ float red[256];
    __shared__ float per_i[NC];
    const int tid = threadIdx.x;   // tid == d index (256 == ND)

    if (tid < NC) cnt_s[tid] = g_counts[tid];
    __syncthreads();
    for (int c = 0; c < NC; c++) {
        float v = g_S[c*ND + tid] / fmaxf(cnt_s[c], 1.f);
        cen[c][tid] = v;
        g_centers[c*ND + tid] = v;
    }
    __syncthreads();
    for (int c = 0; c < NC; c++) {
        float v = cen[c][tid];
        red[tid] = v*v; __syncthreads();
        for (int s = 128; s > 0; s >>= 1) {
            if (tid < s) red[tid] += red[tid+s];
            __syncthreads();
        }
        if (tid == 0) ncen_s[c] = sqrtf(red[0]);
        __syncthreads();
    }
    if (tid < NC) g_ncen[tid] = ncen_s[tid];
    if (tid < NC) per_i[tid] = 0.f;
    __syncthreads();

    for (int p = tid; p < NC*NC; p += 256) {
        int i = p / NC, j = p % NC;
        float dot = 0.f;
        #pragma unroll 8
        for (int dd = 0; dd < ND; dd++) dot += cen[i][dd] * cen[j][dd];
        float s = dot / fmaxf(ncen_s[i]*ncen_s[j], EPS);
        float val = (i == j) ? (1.f - s) : fmaxf(s, 0.f);
        atomicAdd(&per_i[i], val);
    }
    __syncthreads();
    if (tid == 0) {
        float dl = 0.f;
        for (int i = 0; i < NC; i++)
            if (cnt_s[i] > 0.f) dl += per_i[i] / (float)NC;
        g_diff = dl;
    }
}

// ---------------- kernel 3: per-pixel partial dot & normsq over a D-chunk ----------------
// grid = (NPIX/1024) * NCHUNK blocks; 256 threads; thread owns 4 pixels (float4)
__global__ __launch_bounds__(256) void k_pass2(const float4* __restrict__ X,
                                               const int4* __restrict__ T) {
    __shared__ float csh[NC*65];   // [class][dd] padded to 65 -> conflict-free
    const int tid   = threadIdx.x;
    const int chunk = blockIdx.x & (NCHUNK-1);
    const int tile  = blockIdx.x >> 2;           // 0..127, 1024 pixels each
    const int b     = tile >> 4;                 // 16 tiles per batch
    const int px0   = ((tile & 15) << 10) + (tid << 2);

    for (int i = tid; i < NC*DCH; i += 256) {
        int c = i / DCH, dd = i % DCH;
        csh[c*65 + dd] = g_centers[c*ND + chunk*DCH + dd];
    }
    __syncthreads();

    int4 l = T[(b*HW + px0) >> 2];
    const int la = l.x*65, lb = l.y*65, lc = l.z*65, ld = l.w*65;
    const float4* base = X + (size_t)(b*ND + chunk*DCH) * (HW/4) + (px0 >> 2);

    float dx=0,dy=0,dz=0,dw=0, nx=0,ny=0,nz=0,nw=0;
    #pragma unroll 4
    for (int dd = 0; dd < DCH; dd++) {
        float4 v = base[(size_t)dd * (HW/4)];
        dx += v.x * csh[la+dd];  nx += v.x*v.x;
        dy += v.y * csh[lb+dd];  ny += v.y*v.y;
        dz += v.z * csh[lc+dd];  nz += v.z*v.z;
        dw += v.w * csh[ld+dd];  nw += v.w*v.w;
    }
    const int n = tile*1024 + tid*4;
    float4* dp = (float4*)&g_dotp[chunk*NPIX + n];
    float4* np = (float4*)&g_nsqp[chunk*NPIX + n];
    *dp = make_float4(dx,dy,dz,dw);
    *np = make_float4(nx,ny,nz,nw);
}

// ---------------- kernel 4: per-pixel cos -> per-class (1-cos) sums ----------------
__global__ __launch_bounds__(256) void k_finalpix(const int* __restrict__ T) {
    __shared__ float bins[20];
    __shared__ float ncs[NC];
    const int tid = threadIdx.x;
    if (tid < 20) bins[tid] = 0.f;
    if (tid < NC) ncs[tid] = g_ncen[tid];
    __syncthreads();

    const int n = blockIdx.x*256 + tid;
    const int lab = T[n];
    float dot = 0.f, nsq = 0.f;
    #pragma unroll
    for (int c2 = 0; c2 < NCHUNK; c2++) {
        dot += g_dotp[c2*NPIX + n];
        nsq += g_nsqp[c2*NPIX + n];
    }
    float cosv = dot / fmaxf(sqrtf(nsq) * ncs[lab], EPS);
    atomicAdd(&bins[lab], 1.f - cosv);
    __syncthreads();
    if (tid < NC) atomicAdd(&g_percls[tid], bins[tid]);
}

// ---------------- kernel 5: finalize ----------------
__global__ void k_final(float* __restrict__ out) {
    float r = g_diff;
    for (int c = 0; c < NC; c++) {
        float cnt = g_counts[c];
        if (cnt > 0.f) r += g_percls[c] / fmaxf(cnt, 1.f);
    }
    out[0] = r;
}

extern "C" void kernel_launch(void* const* d_in, const int* in_sizes, int n_in,
                              void* d_out, int out_size) {
    const float4* X = (const float4*)d_in[0];   // (8,256,128,128) fp32
    const int4*   T = (const int4*)d_in[1];     // (8,128,128) int32
    float* out = (float*)d_out;

    k_zero<<<(NC*ND + 255)/256, 256>>>();
    k_pass1<<<NB*ND, 256>>>(X, T);
    k_centers<<<1, 256>>>();
    k_pass2<<<(NPIX/1024)*NCHUNK, 256>>>(X, T);
    k_finalpix<<<NPIX/256, 256>>>((const int*)d_in[1]);
    k_final<<<1, 1>>>(out);
}